// round 10
// baseline (speedup 1.0000x reference)
#include <cuda_runtime.h>

// ---------------- Problem constants ----------------
#define NBOX 8000          // 5 anchors * 40 * 40
#define HW 40
#define NCLS 20
#define CHSTRIDE (HW*HW)   // 1600 floats between channels
#define STRIDEPX 8.0f      // 320 / 40

#define NSEG 32            // decode blocks == valid-list segments
#define SEGSZ 256
#define NSLOT (NSEG*SEGSZ) // 8192 linear slots

#define MMASK 256          // mask-matrix fast-path capacity (expected M ~ 200)
#define NW 8               // 256/32
#define CAPC 768           // candidate capacity (sort + mid path)

// ---------------- Scratch (device globals, no allocation) ----------------
__device__ float              d_dec6[NBOX * 6];   // decoded rows, original index order
__device__ unsigned long long d_vkey[NSLOT];      // segmented valid keys: (~conf)<<32 | idx
__device__ unsigned char      d_vcode[NSLOT];     // segmented valid class
__device__ int                d_vcnt[NSEG];       // per-segment valid count (overwritten each launch)
__device__ int                d_cand[NCLS * NBOX];   // fallback only
__device__ int                d_cand2[NCLS * NBOX];  // fallback only

// ---------------- K1: decode + segmented ballot compaction + zero output ----------------
__global__ void k_decode(const float* __restrict__ x, const float* __restrict__ anchors,
                         float* __restrict__ out) {
    __shared__ int wbase[8];
    int tid  = threadIdx.x;
    int b    = blockIdx.x;
    int gid  = b * SEGSZ + tid;
    int lane = tid & 31;
    int warp = tid >> 5;

    // zero output (poisoned before timing)
    for (int k = gid; k < NBOX * 6; k += NSEG * SEGSZ) out[k] = 0.0f;

    int  i   = gid;
    bool inb = (i < NBOX);
    int  ii  = inb ? i : 0;    // clamp for safe loads

    int a   = ii / (HW * HW);
    int rem = ii - a * (HW * HW);
    int gy  = rem / HW;
    int gx  = rem - gy * HW;
    int base = ((a * 25) * HW + gy) * HW + gx;

    // hoist all 25 loads (max MLP)
    float t[5];
#pragma unroll
    for (int k = 0; k < 5; k++) t[k] = x[base + k * CHSTRIDE];
    float cl[NCLS];
#pragma unroll
    for (int c = 0; c < NCLS; c++) cl[c] = x[base + (5 + c) * CHSTRIDE];

    float tx   = 1.0f / (1.0f + expf(-t[0]));
    float ty   = 1.0f / (1.0f + expf(-t[1]));
    float conf = 1.0f / (1.0f + expf(-t[4]));

    float aw = anchors[a * 2 + 0];
    float ah = anchors[a * 2 + 1];

    float bx = (tx + (float)gx) * STRIDEPX;
    float by = (ty + (float)gy) * STRIDEPX;
    float bw = expf(t[2]) * aw * STRIDEPX;
    float bh = expf(t[3]) * ah * STRIDEPX;

    // argmax (strict '>' keeps first occurrence like jnp.argmax)
    float best = cl[0];
    int bc = 0;
#pragma unroll
    for (int c = 1; c < NCLS; c++)
        if (cl[c] > best) { best = cl[c]; bc = c; }

    if (inb) {
        d_dec6[i * 6 + 0] = bx;
        d_dec6[i * 6 + 1] = by;
        d_dec6[i * 6 + 2] = bw;
        d_dec6[i * 6 + 3] = bh;
        d_dec6[i * 6 + 4] = conf;
        d_dec6[i * 6 + 5] = (float)bc;
    }

    // valid (conf > 0.5 <=> logit > 0) -> deterministic segmented compaction
    bool valid = inb && (t[4] > 0.0f);
    unsigned bal = __ballot_sync(0xffffffffu, valid);
    int wp = __popc(bal & ((1u << lane) - 1u));
    if (lane == 0) wbase[warp] = __popc(bal);
    __syncthreads();
    int off = 0;
#pragma unroll
    for (int k = 0; k < 8; k++) if (k < warp) off += wbase[k];
    if (valid) {
        int slot = b * SEGSZ + off + wp;
        unsigned u = __float_as_uint(conf);   // conf in (0,1): bits monotone
        d_vkey[slot]  = ((unsigned long long)(~u) << 32) | (unsigned long long)(unsigned)i;
        d_vcode[slot] = (unsigned char)bc;
    }
    if (tid == 0) {
        int tot = 0;
#pragma unroll
        for (int k = 0; k < 8; k++) tot += wbase[k];
        d_vcnt[b] = tot;
    }
}

// IoU >= 0.5 <=> 2*inter >= union (division-free)
__device__ __forceinline__ bool sup_test(float xi1, float yi1, float xi2, float yi2, float ai,
                                         float xj1, float yj1, float xj2, float yj2, float aj) {
    float iw = fmaxf(fminf(xi2, xj2) - fmaxf(xi1, xj1), 0.0f);
    float ih = fmaxf(fminf(yi2, yj2) - fmaxf(yi1, yj1), 0.0f);
    float inter = iw * ih;
    float denom = ai + aj - inter + 1e-6f;
    return 2.0f * inter >= denom;
}

// warp-cooperative: global rank of key K (# valid keys < K), then lane0 emits row
__device__ __forceinline__ void rank_and_emit(const int* svcnt, unsigned long long K,
                                              int lane, float* out) {
    int cnt = 0;
    for (int vl = lane; vl < NSLOT; vl += 32) {
        int seg = vl >> 8, o = vl & (SEGSZ - 1);
        if (o < svcnt[seg] && d_vkey[vl] < K) cnt++;
    }
#pragma unroll
    for (int s = 16; s > 0; s >>= 1) cnt += __shfl_down_sync(0xffffffffu, cnt, s);
    if (lane == 0) {
        int r = cnt;
        int orig = (int)(unsigned)(K & 0xffffffffu);
#pragma unroll
        for (int k = 0; k < 6; k++) out[6 * r + k] = d_dec6[orig * 6 + k];
    }
}

// ---------------- K2: fused candidate-find + class-sort + NMS + rank + emit ----------------
__global__ void k_nms(float* __restrict__ out) {
    __shared__ int                svcnt[NSEG];
    __shared__ unsigned long long skey[CAPC];    // unordered candidate keys
    __shared__ unsigned long long skeyS[CAPC];   // sorted by key (= conf desc, idx asc)
    __shared__ float    sx1[CAPC], sy1[CAPC], sx2[CAPC], sy2[CAPC], sar[CAPC];
    __shared__ unsigned smask[MMASK * NW];
    __shared__ unsigned srow[NW], skw[NW];
    __shared__ int      skept[CAPC];
    __shared__ int      sM, snk;

    int c    = blockIdx.x;
    int tid  = threadIdx.x;
    int lane = tid & 31;
    int warp = tid >> 5;

    if (tid < NSEG) svcnt[tid] = d_vcnt[tid];
    if (tid == 0) { sM = 0; snk = 0; }
    if (tid < NW) srow[tid] = 0;
    __syncthreads();

    // ---- find candidates of class c across segments ----
    for (int vl = tid; vl < NSLOT; vl += 512) {
        int seg = vl >> 8, o = vl & (SEGSZ - 1);
        if (o < svcnt[seg] && d_vcode[vl] == (unsigned char)c) {
            int slot = atomicAdd(&sM, 1);
            if (slot < CAPC) skey[slot] = d_vkey[vl];
        }
    }
    __syncthreads();
    int M = sM;
    if (M == 0) return;

    if (M <= CAPC) {
        // ---- in-block rank-sort by key (unique keys -> permutation) ----
        for (int t = tid; t < M; t += 512) {
            unsigned long long my = skey[t];
            int pos = 0;
            for (int j = 0; j < M; j++) pos += (skey[j] < my) ? 1 : 0;  // broadcast LDS
            skeyS[pos] = my;
        }
        __syncthreads();
        // ---- gather geometry in sorted order ----
        for (int t = tid; t < M; t += 512) {
            int orig = (int)(unsigned)(skeyS[t] & 0xffffffffu);
            float cx = d_dec6[orig * 6 + 0];
            float cy = d_dec6[orig * 6 + 1];
            float w  = d_dec6[orig * 6 + 2];
            float h  = d_dec6[orig * 6 + 3];
            float x1 = cx - 0.5f * w, y1 = cy - 0.5f * h;
            float x2 = cx + 0.5f * w, y2 = cy + 0.5f * h;
            sx1[t] = x1; sy1[t] = y1; sx2[t] = x2; sy2[t] = y2;
            sar[t] = fabsf((x2 - x1) * (y2 - y1));
        }
        __syncthreads();

        if (M <= MMASK) {
            // ---- ballot mask fill: one warp per row ----
            int nw = (M + 31) >> 5;
            for (int i = warp; i < M; i += 16) {
                float xi1 = sx1[i], yi1 = sy1[i], xi2 = sx2[i], yi2 = sy2[i], ai = sar[i];
                int wq0 = (i + 1) >> 5;
                unsigned rowany = 0;
                if (lane == 0)
                    for (int q = 0; q < wq0; q++) smask[i * NW + q] = 0;
                for (int wq = wq0; wq < nw; wq++) {
                    int j = (wq << 5) + lane;
                    bool s = (j > i) && (j < M) &&
                             sup_test(xi1, yi1, xi2, yi2, ai,
                                      sx1[j], sy1[j], sx2[j], sy2[j], sar[j]);
                    unsigned bits = __ballot_sync(0xffffffffu, s);
                    if (lane == 0) smask[i * NW + wq] = bits;
                    rowany |= bits;
                }
                if (lane == 0 && rowany) atomicOr(&srow[i >> 5], 1u << (i & 31));
            }
            __syncthreads();

            // ---- single-thread register sweep ----
            if (tid == 0) {
                unsigned kw[NW];
#pragma unroll
                for (int q = 0; q < NW; q++) {
                    int lo = q * 32;
                    unsigned v = 0;
                    if (lo < M) {
                        int rem = M - lo;
                        v = (rem >= 32) ? 0xffffffffu : ((1u << rem) - 1u);
                    }
                    kw[q] = v;
                }
                int nwl = (M + 31) >> 5;
                for (int w = 0; w < nwl; w++) {
                    unsigned active = kw[w] & srow[w];
                    while (active) {
                        int b = __ffs(active) - 1;
                        int i = w * 32 + b;
#pragma unroll
                        for (int q = 0; q < NW; q++)
                            kw[q] &= ~smask[i * NW + q];
                        active = kw[w] & srow[w] & (0xfffffffeu << b);
                    }
                }
#pragma unroll
                for (int q = 0; q < NW; q++) skw[q] = kw[q];
            }
            __syncthreads();
            // collect kept slots
            for (int t = tid; t < M; t += 512)
                if ((skw[t >> 5] >> (t & 31)) & 1u) skept[atomicAdd(&snk, 1)] = t;
            __syncthreads();
        } else {
            // ---- mid path (MMASK < M <= CAPC): pivot loop, keep bytes overlay smask ----
            unsigned char* skbyte = (unsigned char*)smask;   // 8192B >= CAPC
            for (int t = tid; t < M; t += 512) skbyte[t] = 1;
            __syncthreads();
            for (int i = 0; i < M - 1; i++) {
                __syncthreads();
                if (!skbyte[i]) continue;
                float xi1 = sx1[i], yi1 = sy1[i], xi2 = sx2[i], yi2 = sy2[i], ai = sar[i];
                for (int j = i + 1 + tid; j < M; j += 512) {
                    if (!skbyte[j]) continue;
                    if (sup_test(xi1, yi1, xi2, yi2, ai,
                                 sx1[j], sy1[j], sx2[j], sy2[j], sar[j]))
                        skbyte[j] = 0;
                }
            }
            __syncthreads();
            for (int t = tid; t < M; t += 512)
                if (skbyte[t]) skept[atomicAdd(&snk, 1)] = t;
            __syncthreads();
        }

        // ---- global rank + emit for kept boxes: warp per kept ----
        int nk = snk;
        for (int k = warp; k < nk; k += 16)
            rank_and_emit(svcnt, skeyS[skept[k]], lane, out);
    } else {
        // ---- fallback (M > CAPC, never expected): global O(M^2) sort + pivot loop ----
        if (tid == 0) sM = 0;
        __syncthreads();
        for (int vl = tid; vl < NSLOT; vl += 512) {
            int seg = vl >> 8, o = vl & (SEGSZ - 1);
            if (o < svcnt[seg] && d_vcode[vl] == (unsigned char)c)
                d_cand[c * NBOX + atomicAdd(&sM, 1)] = vl;
        }
        __syncthreads();
        for (int t = tid; t < M; t += 512) {
            unsigned long long my = d_vkey[d_cand[c * NBOX + t]];
            int pos = 0;
            for (int j = 0; j < M; j++)
                pos += (d_vkey[d_cand[c * NBOX + j]] < my) ? 1 : 0;
            d_cand2[c * NBOX + pos] = d_cand[c * NBOX + t];
        }
        __syncthreads();
        unsigned char* skbyte = (unsigned char*)skey;   // 6144+6144B >= 8000? use both arrays
        // M <= NBOX = 8000; skey+skeyS contiguous? Not guaranteed — use skey (6144) + check.
        // Safe: use sx1 region (CAPC*5*4 = 15360 bytes >= 8000).
        skbyte = (unsigned char*)sx1;
        for (int t = tid; t < M; t += 512) skbyte[t] = 1;
        __syncthreads();
        for (int i = 0; i < M - 1; i++) {
            __syncthreads();
            if (!skbyte[i]) continue;
            int oi = (int)(unsigned)(d_vkey[d_cand2[c * NBOX + i]] & 0xffffffffu);
            float cx = d_dec6[oi * 6 + 0], cy = d_dec6[oi * 6 + 1];
            float w  = d_dec6[oi * 6 + 2], h  = d_dec6[oi * 6 + 3];
            float xi1 = cx - 0.5f * w, yi1 = cy - 0.5f * h;
            float xi2 = cx + 0.5f * w, yi2 = cy + 0.5f * h;
            float ai = fabsf((xi2 - xi1) * (yi2 - yi1));
            for (int j = i + 1 + tid; j < M; j += 512) {
                if (!skbyte[j]) continue;
                int oj = (int)(unsigned)(d_vkey[d_cand2[c * NBOX + j]] & 0xffffffffu);
                float cxj = d_dec6[oj * 6 + 0], cyj = d_dec6[oj * 6 + 1];
                float wj  = d_dec6[oj * 6 + 2], hj  = d_dec6[oj * 6 + 3];
                float xj1 = cxj - 0.5f * wj, yj1 = cyj - 0.5f * hj;
                float xj2 = cxj + 0.5f * wj, yj2 = cyj + 0.5f * hj;
                float aj = fabsf((xj2 - xj1) * (yj2 - yj1));
                if (sup_test(xi1, yi1, xi2, yi2, ai, xj1, yj1, xj2, yj2, aj))
                    skbyte[j] = 0;
            }
        }
        __syncthreads();
        for (int t = warp; t < M; t += 16)
            if (skbyte[t])
                rank_and_emit(svcnt, d_vkey[d_cand2[c * NBOX + t]], lane, out);
    }
}

// ---------------- launch ----------------
extern "C" void kernel_launch(void* const* d_in, const int* in_sizes, int n_in,
                              void* d_out, int out_size) {
    const float* x;
    const float* anchors;
    if (in_sizes[0] == 10) { anchors = (const float*)d_in[0]; x = (const float*)d_in[1]; }
    else                   { x = (const float*)d_in[0]; anchors = (const float*)d_in[1]; }
    float* out = (float*)d_out;

    k_decode <<<NSEG, SEGSZ>>>(x, anchors, out);
    k_nms    <<<NCLS, 512>>>(out);
}

// round 11
// speedup vs baseline: 1.2764x; 1.2764x over previous
#include <cuda_runtime.h>

// ---------------- Problem constants ----------------
#define NBOX 8000          // 5 anchors * 40 * 40
#define HW 40
#define NCLS 20
#define CHSTRIDE (HW*HW)   // 1600 floats between channels
#define STRIDEPX 8.0f      // 320 / 40

#define NSEG 32            // decode blocks == valid-list segments
#define SEGSZ 256
#define NSLOT (NSEG*SEGSZ) // 8192 linear slots
#define NBATCH 16          // NSLOT / 512

#define MMASK 256          // mask-matrix fast-path capacity (expected M ~ 200)
#define NW 8               // 256/32
#define CAPC 768           // candidate capacity (sort + mid path)

// ---------------- Scratch (device globals, no allocation) ----------------
__device__ float              d_dec6[NBOX * 6];   // decoded rows, original index order
__device__ unsigned long long d_vkey[NSLOT];      // segmented valid keys: (~conf)<<32 | idx
__device__ unsigned char      d_vcode[NSLOT];     // segmented valid class
__device__ int                d_vcnt[NSEG];       // per-segment valid count (overwritten each launch)
__device__ int                d_cand[NCLS * NBOX];   // fallback only
__device__ int                d_cand2[NCLS * NBOX];  // fallback only

// ---------------- K1: decode + segmented ballot compaction + zero output ----------------
__global__ void k_decode(const float* __restrict__ x, const float* __restrict__ anchors,
                         float* __restrict__ out) {
    __shared__ int wbase[8];
    int tid  = threadIdx.x;
    int b    = blockIdx.x;
    int gid  = b * SEGSZ + tid;
    int lane = tid & 31;
    int warp = tid >> 5;

    // zero output (poisoned before timing)
    for (int k = gid; k < NBOX * 6; k += NSEG * SEGSZ) out[k] = 0.0f;

    int  i   = gid;
    bool inb = (i < NBOX);
    int  ii  = inb ? i : 0;    // clamp for safe loads

    int a   = ii / (HW * HW);
    int rem = ii - a * (HW * HW);
    int gy  = rem / HW;
    int gx  = rem - gy * HW;
    int base = ((a * 25) * HW + gy) * HW + gx;

    // hoist all 25 loads (max MLP)
    float t[5];
#pragma unroll
    for (int k = 0; k < 5; k++) t[k] = x[base + k * CHSTRIDE];
    float cl[NCLS];
#pragma unroll
    for (int c = 0; c < NCLS; c++) cl[c] = x[base + (5 + c) * CHSTRIDE];

    float tx   = 1.0f / (1.0f + expf(-t[0]));
    float ty   = 1.0f / (1.0f + expf(-t[1]));
    float conf = 1.0f / (1.0f + expf(-t[4]));

    float aw = anchors[a * 2 + 0];
    float ah = anchors[a * 2 + 1];

    float bx = (tx + (float)gx) * STRIDEPX;
    float by = (ty + (float)gy) * STRIDEPX;
    float bw = expf(t[2]) * aw * STRIDEPX;
    float bh = expf(t[3]) * ah * STRIDEPX;

    // argmax (strict '>' keeps first occurrence like jnp.argmax)
    float best = cl[0];
    int bc = 0;
#pragma unroll
    for (int c = 1; c < NCLS; c++)
        if (cl[c] > best) { best = cl[c]; bc = c; }

    if (inb) {
        d_dec6[i * 6 + 0] = bx;
        d_dec6[i * 6 + 1] = by;
        d_dec6[i * 6 + 2] = bw;
        d_dec6[i * 6 + 3] = bh;
        d_dec6[i * 6 + 4] = conf;
        d_dec6[i * 6 + 5] = (float)bc;
    }

    // valid (conf > 0.5 <=> logit > 0) -> deterministic segmented compaction
    bool valid = inb && (t[4] > 0.0f);
    unsigned bal = __ballot_sync(0xffffffffu, valid);
    int wp = __popc(bal & ((1u << lane) - 1u));
    if (lane == 0) wbase[warp] = __popc(bal);
    __syncthreads();
    int off = 0;
#pragma unroll
    for (int k = 0; k < 8; k++) if (k < warp) off += wbase[k];
    if (valid) {
        int slot = b * SEGSZ + off + wp;
        unsigned u = __float_as_uint(conf);   // conf in (0,1): bits monotone
        d_vkey[slot]  = ((unsigned long long)(~u) << 32) | (unsigned long long)(unsigned)i;
        d_vcode[slot] = (unsigned char)bc;
    }
    if (tid == 0) {
        int tot = 0;
#pragma unroll
        for (int k = 0; k < 8; k++) tot += wbase[k];
        d_vcnt[b] = tot;
    }
}

// IoU >= 0.5 <=> 2*inter >= union (division-free)
__device__ __forceinline__ bool sup_test(float xi1, float yi1, float xi2, float yi2, float ai,
                                         float xj1, float yj1, float xj2, float yj2, float aj) {
    float iw = fmaxf(fminf(xi2, xj2) - fmaxf(xi1, xj1), 0.0f);
    float ih = fmaxf(fminf(yi2, yj2) - fmaxf(yi1, yj1), 0.0f);
    float inter = iw * ih;
    float denom = ai + aj - inter + 1e-6f;
    return 2.0f * inter >= denom;
}

// fallback only: warp-cooperative global rank + emit (slow path, never hit in practice)
__device__ __forceinline__ void rank_and_emit(const int* svcnt, unsigned long long K,
                                              int lane, float* out) {
    int cnt = 0;
#pragma unroll 8
    for (int vl = lane; vl < NSLOT; vl += 32) {
        int seg = vl >> 8, o = vl & (SEGSZ - 1);
        if (o < svcnt[seg] && d_vkey[vl] < K) cnt++;
    }
#pragma unroll
    for (int s = 16; s > 0; s >>= 1) cnt += __shfl_down_sync(0xffffffffu, cnt, s);
    if (lane == 0) {
        int r = cnt;
        int orig = (int)(unsigned)(K & 0xffffffffu);
#pragma unroll
        for (int k = 0; k < 6; k++) out[6 * r + k] = d_dec6[orig * 6 + k];
    }
}

// ---------------- K2: fused candidate-find + class-sort + NMS + rank + emit ----------------
__global__ void k_nms(float* __restrict__ out) {
    __shared__ int                svcnt[NSEG];
    __shared__ unsigned long long skey[CAPC];    // unordered candidate keys
    __shared__ unsigned long long skeyS[CAPC];   // sorted by key (= conf desc, idx asc)
    __shared__ float    sx1[CAPC], sy1[CAPC], sx2[CAPC], sy2[CAPC], sar[CAPC];
    __shared__ unsigned smask[MMASK * NW];
    __shared__ unsigned srow[NW], skw[NW];
    __shared__ int      skept[CAPC];
    __shared__ int      srank[CAPC];
    __shared__ int      sM, snk;

    int c    = blockIdx.x;
    int tid  = threadIdx.x;
    int lane = tid & 31;
    int warp = tid >> 5;

    if (tid < NSEG) svcnt[tid] = d_vcnt[tid];
    if (tid == 0) { sM = 0; snk = 0; }
    if (tid < NW) srow[tid] = 0;
    __syncthreads();

    // ---- A: find candidates of class c (batched loads, no exposed latency) ----
    {
        unsigned char mc[NBATCH];
#pragma unroll
        for (int b = 0; b < NBATCH; b++) mc[b] = d_vcode[tid + b * 512];
#pragma unroll
        for (int b = 0; b < NBATCH; b++) {
            int vl = tid + b * 512;
            int seg = vl >> 8, o = vl & (SEGSZ - 1);
            if (o < svcnt[seg] && mc[b] == (unsigned char)c) {
                int slot = atomicAdd(&sM, 1);
                if (slot < CAPC) skey[slot] = d_vkey[vl];
            }
        }
    }
    __syncthreads();
    int M = sM;
    if (M == 0) return;

    if (M <= CAPC) {
        // ---- B: in-block rank-sort by key (unique keys -> permutation) ----
        for (int t = tid; t < M; t += 512) {
            unsigned long long my = skey[t];
            int pos = 0;
#pragma unroll 8
            for (int j = 0; j < M; j++) pos += (skey[j] < my) ? 1 : 0;
            skeyS[pos] = my;
        }
        __syncthreads();
        // ---- C: gather geometry in sorted order ----
        for (int t = tid; t < M; t += 512) {
            int orig = (int)(unsigned)(skeyS[t] & 0xffffffffu);
            float cx = d_dec6[orig * 6 + 0];
            float cy = d_dec6[orig * 6 + 1];
            float w  = d_dec6[orig * 6 + 2];
            float h  = d_dec6[orig * 6 + 3];
            float x1 = cx - 0.5f * w, y1 = cy - 0.5f * h;
            float x2 = cx + 0.5f * w, y2 = cy + 0.5f * h;
            sx1[t] = x1; sy1[t] = y1; sx2[t] = x2; sy2[t] = y2;
            sar[t] = fabsf((x2 - x1) * (y2 - y1));
        }
        __syncthreads();

        if (M <= MMASK) {
            // ---- D: ballot mask fill, one warp per row ----
            int nw = (M + 31) >> 5;
            for (int i = warp; i < M; i += 16) {
                float xi1 = sx1[i], yi1 = sy1[i], xi2 = sx2[i], yi2 = sy2[i], ai = sar[i];
                int wq0 = (i + 1) >> 5;
                unsigned rowany = 0;
                if (lane == 0)
                    for (int q = 0; q < wq0; q++) smask[i * NW + q] = 0;
                for (int wq = wq0; wq < nw; wq++) {
                    int j = (wq << 5) + lane;
                    bool s = (j > i) && (j < M) &&
                             sup_test(xi1, yi1, xi2, yi2, ai,
                                      sx1[j], sy1[j], sx2[j], sy2[j], sar[j]);
                    unsigned bits = __ballot_sync(0xffffffffu, s);
                    if (lane == 0) smask[i * NW + wq] = bits;
                    rowany |= bits;
                }
                if (lane == 0 && rowany) atomicOr(&srow[i >> 5], 1u << (i & 31));
            }
            __syncthreads();

            // ---- single-thread register sweep ----
            if (tid == 0) {
                unsigned kw[NW];
#pragma unroll
                for (int q = 0; q < NW; q++) {
                    int lo = q * 32;
                    unsigned v = 0;
                    if (lo < M) {
                        int rem = M - lo;
                        v = (rem >= 32) ? 0xffffffffu : ((1u << rem) - 1u);
                    }
                    kw[q] = v;
                }
                int nwl = (M + 31) >> 5;
                for (int w = 0; w < nwl; w++) {
                    unsigned active = kw[w] & srow[w];
                    while (active) {
                        int b = __ffs(active) - 1;
                        int i = w * 32 + b;
#pragma unroll
                        for (int q = 0; q < NW; q++)
                            kw[q] &= ~smask[i * NW + q];
                        active = kw[w] & srow[w] & (0xfffffffeu << b);
                    }
                }
#pragma unroll
                for (int q = 0; q < NW; q++) skw[q] = kw[q];
            }
            __syncthreads();
            for (int t = tid; t < M; t += 512)
                if ((skw[t >> 5] >> (t & 31)) & 1u) skept[atomicAdd(&snk, 1)] = t;
            __syncthreads();
        } else {
            // ---- mid path (MMASK < M <= CAPC): pivot loop ----
            unsigned char* skbyte = (unsigned char*)smask;   // 8192B >= CAPC
            for (int t = tid; t < M; t += 512) skbyte[t] = 1;
            __syncthreads();
            for (int i = 0; i < M - 1; i++) {
                __syncthreads();
                if (!skbyte[i]) continue;
                float xi1 = sx1[i], yi1 = sy1[i], xi2 = sx2[i], yi2 = sy2[i], ai = sar[i];
                for (int j = i + 1 + tid; j < M; j += 512) {
                    if (!skbyte[j]) continue;
                    if (sup_test(xi1, yi1, xi2, yi2, ai,
                                 sx1[j], sy1[j], sx2[j], sy2[j], sar[j]))
                        skbyte[j] = 0;
                }
            }
            __syncthreads();
            for (int t = tid; t < M; t += 512)
                if (skbyte[t]) skept[atomicAdd(&snk, 1)] = t;
            __syncthreads();
        }

        // ---- E: cooperative global rank for kept boxes, then emit ----
        int nk = snk;
        if (nk > 0) {
            for (int k = tid; k < nk; k += 512) srank[k] = 0;
            __syncthreads();
            // preload this thread's 16 slot keys (batched; invalid -> MAX, never < real key)
            unsigned long long myk[NBATCH];
#pragma unroll
            for (int b = 0; b < NBATCH; b++) {
                int vl = tid + b * 512;
                int seg = vl >> 8, o = vl & (SEGSZ - 1);
                myk[b] = (o < svcnt[seg]) ? d_vkey[vl] : 0xFFFFFFFFFFFFFFFFull;
            }
            for (int k = 0; k < nk; k++) {
                unsigned long long K = skeyS[skept[k]];
                int cnt = 0;
#pragma unroll
                for (int b = 0; b < NBATCH; b++) cnt += (myk[b] < K) ? 1 : 0;
#pragma unroll
                for (int s = 16; s > 0; s >>= 1)
                    cnt += __shfl_down_sync(0xffffffffu, cnt, s);
                if (lane == 0 && cnt) atomicAdd(&srank[k], cnt);
            }
            __syncthreads();
            for (int k = tid; k < nk; k += 512) {
                unsigned long long K = skeyS[skept[k]];
                int r = srank[k];
                int orig = (int)(unsigned)(K & 0xffffffffu);
#pragma unroll
                for (int q = 0; q < 6; q++) out[6 * r + q] = d_dec6[orig * 6 + q];
            }
        }
    } else {
        // ---- fallback (M > CAPC, never expected): global O(M^2) sort + pivot loop ----
        if (tid == 0) sM = 0;
        __syncthreads();
        for (int vl = tid; vl < NSLOT; vl += 512) {
            int seg = vl >> 8, o = vl & (SEGSZ - 1);
            if (o < svcnt[seg] && d_vcode[vl] == (unsigned char)c)
                d_cand[c * NBOX + atomicAdd(&sM, 1)] = vl;
        }
        __syncthreads();
        for (int t = tid; t < M; t += 512) {
            unsigned long long my = d_vkey[d_cand[c * NBOX + t]];
            int pos = 0;
#pragma unroll 4
            for (int j = 0; j < M; j++)
                pos += (d_vkey[d_cand[c * NBOX + j]] < my) ? 1 : 0;
            d_cand2[c * NBOX + pos] = d_cand[c * NBOX + t];
        }
        __syncthreads();
        unsigned char* skbyte = (unsigned char*)sx1;     // 15360 bytes >= 8000 >= M
        for (int t = tid; t < M; t += 512) skbyte[t] = 1;
        __syncthreads();
        for (int i = 0; i < M - 1; i++) {
            __syncthreads();
            if (!skbyte[i]) continue;
            int oi = (int)(unsigned)(d_vkey[d_cand2[c * NBOX + i]] & 0xffffffffu);
            float cx = d_dec6[oi * 6 + 0], cy = d_dec6[oi * 6 + 1];
            float w  = d_dec6[oi * 6 + 2], h  = d_dec6[oi * 6 + 3];
            float xi1 = cx - 0.5f * w, yi1 = cy - 0.5f * h;
            float xi2 = cx + 0.5f * w, yi2 = cy + 0.5f * h;
            float ai = fabsf((xi2 - xi1) * (yi2 - yi1));
            for (int j = i + 1 + tid; j < M; j += 512) {
                if (!skbyte[j]) continue;
                int oj = (int)(unsigned)(d_vkey[d_cand2[c * NBOX + j]] & 0xffffffffu);
                float cxj = d_dec6[oj * 6 + 0], cyj = d_dec6[oj * 6 + 1];
                float wj  = d_dec6[oj * 6 + 2], hj  = d_dec6[oj * 6 + 3];
                float xj1 = cxj - 0.5f * wj, yj1 = cyj - 0.5f * hj;
                float xj2 = cxj + 0.5f * wj, yj2 = cyj + 0.5f * hj;
                float aj = fabsf((xj2 - xj1) * (yj2 - yj1));
                if (sup_test(xi1, yi1, xi2, yi2, ai, xj1, yj1, xj2, yj2, aj))
                    skbyte[j] = 0;
            }
        }
        __syncthreads();
        for (int t = warp; t < M; t += 16)
            if (skbyte[t])
                rank_and_emit(svcnt, d_vkey[d_cand2[c * NBOX + t]], lane, out);
    }
}

// ---------------- launch ----------------
extern "C" void kernel_launch(void* const* d_in, const int* in_sizes, int n_in,
                              void* d_out, int out_size) {
    const float* x;
    const float* anchors;
    if (in_sizes[0] == 10) { anchors = (const float*)d_in[0]; x = (const float*)d_in[1]; }
    else                   { x = (const float*)d_in[0]; anchors = (const float*)d_in[1]; }
    float* out = (float*)d_out;

    k_decode <<<NSEG, SEGSZ>>>(x, anchors, out);
    k_nms    <<<NCLS, 512>>>(out);
}

// round 12
// speedup vs baseline: 3.5432x; 2.7758x over previous
#include <cuda_runtime.h>

// ---------------- Problem constants ----------------
#define NBOX 8000          // 5 anchors * 40 * 40
#define HW 40
#define NCLS 20
#define CHSTRIDE (HW*HW)   // 1600 floats between channels
#define STRIDEPX 8.0f      // 320 / 40

#define JC 16
#define CHUNKMAX 500       // ceil(8000/16)
#define IGROUPS 32         // 32*256 = 8192 >= NV

#define MMASK 256          // mask-matrix fast-path capacity (expected M ~ 200)
#define NW 8               // 256/32
#define CAP2 1024          // per-class precomputed-slot capacity (mid path)

// ---------------- Scratch (device globals, no allocation) ----------------
__device__ float              d_dec6[NBOX * 6];      // decoded rows, original index order
__device__ unsigned long long d_vkey[NBOX];          // valid keys: (~bits(conf))<<32 | idx
__device__ unsigned char      d_vcode[NBOX];         // valid class
__device__ int                d_nv;                  // valid count accumulator
__device__ int                d_nv2;                 // snapshot (set by k_rank)
__device__ unsigned           d_partial[JC * NBOX];  // packed: rank | cls_rank<<16
__device__ int                d_cnt[NCLS];           // per-class candidate count
__device__ float4             d_cg4 [NCLS * CAP2];   // slot (cls,rc): x1,y1,x2,y2
__device__ float              d_car [NCLS * CAP2];   // slot: area
__device__ int                d_cr  [NCLS * CAP2];   // slot: output row (global rank)
__device__ float              d_crow6[NCLS * CAP2 * 6]; // slot: full output row
__device__ int                d_cand[NCLS * NBOX];   // fallback only: r | orig<<16

// ---------------- K1: decode + valid append + zero output/counters ----------------
__global__ void k_decode(const float* __restrict__ x, const float* __restrict__ anchors,
                         float* __restrict__ out) {
    int tid = threadIdx.x;
    int gid = blockIdx.x * 256 + tid;

    // zero output (poisoned before timing) and class counters
    for (int k = gid; k < NBOX * 6; k += 32 * 256) out[k] = 0.0f;
    if (gid < NCLS) d_cnt[gid] = 0;

    int  i   = gid;
    bool inb = (i < NBOX);
    int  ii  = inb ? i : 0;    // clamp for safe loads

    int a   = ii / (HW * HW);
    int rem = ii - a * (HW * HW);
    int gy  = rem / HW;
    int gx  = rem - gy * HW;
    int base = ((a * 25) * HW + gy) * HW + gx;

    // hoist all 25 loads (max MLP)
    float t[5];
#pragma unroll
    for (int k = 0; k < 5; k++) t[k] = x[base + k * CHSTRIDE];
    float cl[NCLS];
#pragma unroll
    for (int c = 0; c < NCLS; c++) cl[c] = x[base + (5 + c) * CHSTRIDE];

    float tx   = 1.0f / (1.0f + expf(-t[0]));
    float ty   = 1.0f / (1.0f + expf(-t[1]));
    float conf = 1.0f / (1.0f + expf(-t[4]));

    float aw = anchors[a * 2 + 0];
    float ah = anchors[a * 2 + 1];

    float bx = (tx + (float)gx) * STRIDEPX;
    float by = (ty + (float)gy) * STRIDEPX;
    float bw = expf(t[2]) * aw * STRIDEPX;
    float bh = expf(t[3]) * ah * STRIDEPX;

    // argmax (strict '>' keeps first occurrence like jnp.argmax)
    float best = cl[0];
    int bc = 0;
#pragma unroll
    for (int c = 1; c < NCLS; c++)
        if (cl[c] > best) { best = cl[c]; bc = c; }

    if (!inb) return;

    d_dec6[i * 6 + 0] = bx;
    d_dec6[i * 6 + 1] = by;
    d_dec6[i * 6 + 2] = bw;
    d_dec6[i * 6 + 3] = bh;
    d_dec6[i * 6 + 4] = conf;
    d_dec6[i * 6 + 5] = (float)bc;

    // valid (conf > 0.5 <=> logit > 0): contiguous append.
    // Slot order nondeterministic; ranks are value-based -> deterministic output.
    if (t[4] > 0.0f) {
        int slot = atomicAdd(&d_nv, 1);
        unsigned u = __float_as_uint(conf);     // conf in (0,1): bits monotone
        d_vkey[slot]  = ((unsigned long long)(~u) << 32) | (unsigned long long)(unsigned)i;
        d_vcode[slot] = (unsigned char)bc;
    }
}

// ---------------- K2: chunked rank over valid boxes (+ snapshot NV) ----------------
__global__ void k_rank() {
    __shared__ unsigned long long sk[CHUNKMAX];
    __shared__ unsigned char     sc[CHUNKMAX];
    int NV = d_nv;
    if (blockIdx.x == 0 && threadIdx.x == 0) d_nv2 = NV;
    int CS = (NV + JC - 1) / JC;
    int g = blockIdx.x / JC;
    int c = blockIdx.x - g * JC;
    int j0 = c * CS;
    int cnt = NV - j0; if (cnt > CS) cnt = CS; if (cnt < 0) cnt = 0;
    for (int t = threadIdx.x; t < cnt; t += 256) {
        sk[t] = d_vkey[j0 + t];
        sc[t] = d_vcode[j0 + t];
    }
    __syncthreads();
    int i = g * 256 + threadIdx.x;
    if (i < NV) {
        unsigned long long my = d_vkey[i];
        unsigned char myc = d_vcode[i];
        unsigned acc = 0;
#pragma unroll 8
        for (int j = 0; j < cnt; j++) {
            bool lt = sk[j] < my;
            acc += lt ? (1u + (((sc[j] == myc) ? 1u : 0u) << 16)) : 0u;
        }
        d_partial[c * NBOX + i] = acc;
    }
}

// ---------------- K2b: scatter -> per-class precomputed slots ----------------
__global__ void k_scatter() {
    int i = blockIdx.x * 256 + threadIdx.x;
    int NV = d_nv;
    if (i >= NV) return;
    unsigned s = 0;
#pragma unroll
    for (int c = 0; c < JC; c++) s += d_partial[c * NBOX + i];
    int r  = (int)(s & 0xffffu);   // global rank among valid == output row
    int rc = (int)(s >> 16);       // class rank (unique within class)
    unsigned long long key = d_vkey[i];
    int orig = (int)(unsigned)(key & 0xffffffffu);
    int cls  = (int)d_vcode[i];
    atomicAdd(&d_cnt[cls], 1);
    if (rc < NBOX) d_cand[cls * NBOX + rc] = r | (orig << 16);  // fallback path
    if (rc < CAP2) {
        float cx = d_dec6[orig * 6 + 0];
        float cy = d_dec6[orig * 6 + 1];
        float w  = d_dec6[orig * 6 + 2];
        float h  = d_dec6[orig * 6 + 3];
        float x1 = cx - 0.5f * w, y1 = cy - 0.5f * h;
        float x2 = cx + 0.5f * w, y2 = cy + 0.5f * h;
        int slot = cls * CAP2 + rc;
        d_cg4[slot] = make_float4(x1, y1, x2, y2);
        d_car[slot] = fabsf((x2 - x1) * (y2 - y1));
        d_cr [slot] = r;
        d_crow6[slot * 6 + 0] = cx;
        d_crow6[slot * 6 + 1] = cy;
        d_crow6[slot * 6 + 2] = w;
        d_crow6[slot * 6 + 3] = h;
        d_crow6[slot * 6 + 4] = d_dec6[orig * 6 + 4];
        d_crow6[slot * 6 + 5] = d_dec6[orig * 6 + 5];
    }
}

// IoU >= 0.5 <=> 2*inter >= union (division-free)
__device__ __forceinline__ bool sup_test(float xi1, float yi1, float xi2, float yi2, float ai,
                                         float xj1, float yj1, float xj2, float yj2, float aj) {
    float iw = fmaxf(fminf(xi2, xj2) - fmaxf(xi1, xj1), 0.0f);
    float ih = fmaxf(fminf(yi2, yj2) - fmaxf(yi1, yj1), 0.0f);
    float inter = iw * ih;
    float denom = ai + aj - inter + 1e-6f;
    return 2.0f * inter >= denom;
}

// ---------------- K3: per-class NMS (pure: load -> fill -> sweep -> emit) ----------------
__global__ void k_nms(float* __restrict__ out) {
    __shared__ float    sx1[CAP2], sy1[CAP2], sx2[CAP2], sy2[CAP2], sar[CAP2];
    __shared__ int      sr[CAP2];
    __shared__ unsigned smask[MMASK * NW];
    __shared__ unsigned srow[NW], skw[NW];

    int c    = blockIdx.x;
    int tid  = threadIdx.x;
    int lane = tid & 31;
    int warp = tid >> 5;

    if (c == 0 && tid == 0) d_nv = 0;   // reset accumulator for next graph replay
    if (tid < NW) srow[tid] = 0;

    int M = d_cnt[c];
    if (M == 0) return;

    if (M <= CAP2) {
        // ---- coalesced load of precomputed per-class slots ----
        for (int t = tid; t < M; t += 512) {
            float4 g = d_cg4[c * CAP2 + t];
            sx1[t] = g.x; sy1[t] = g.y; sx2[t] = g.z; sy2[t] = g.w;
            sar[t] = d_car[c * CAP2 + t];
            sr [t] = d_cr [c * CAP2 + t];
        }
        __syncthreads();

        if (M <= MMASK) {
            // ---- ballot mask fill: one warp per row ----
            int nw = (M + 31) >> 5;
            for (int i = warp; i < M; i += 16) {
                float xi1 = sx1[i], yi1 = sy1[i], xi2 = sx2[i], yi2 = sy2[i], ai = sar[i];
                int wq0 = (i + 1) >> 5;
                unsigned rowany = 0;
                if (lane == 0)
                    for (int q = 0; q < wq0; q++) smask[i * NW + q] = 0;
                for (int wq = wq0; wq < nw; wq++) {
                    int j = (wq << 5) + lane;
                    bool s = (j > i) && (j < M) &&
                             sup_test(xi1, yi1, xi2, yi2, ai,
                                      sx1[j], sy1[j], sx2[j], sy2[j], sar[j]);
                    unsigned bits = __ballot_sync(0xffffffffu, s);
                    if (lane == 0) smask[i * NW + wq] = bits;
                    rowany |= bits;
                }
                if (lane == 0 && rowany) atomicOr(&srow[i >> 5], 1u << (i & 31));
            }
            __syncthreads();

            // ---- single-thread register sweep (skip non-suppressing pivots) ----
            if (tid == 0) {
                unsigned kw[NW];
#pragma unroll
                for (int q = 0; q < NW; q++) {
                    int lo = q * 32;
                    unsigned v = 0;
                    if (lo < M) {
                        int rem = M - lo;
                        v = (rem >= 32) ? 0xffffffffu : ((1u << rem) - 1u);
                    }
                    kw[q] = v;
                }
                int nwl = (M + 31) >> 5;
                for (int w = 0; w < nwl; w++) {
                    unsigned active = kw[w] & srow[w];
                    while (active) {
                        int b = __ffs(active) - 1;
                        int i = w * 32 + b;
#pragma unroll
                        for (int q = 0; q < NW; q++)
                            kw[q] &= ~smask[i * NW + q];   // rows hold only j>i bits
                        active = kw[w] & srow[w] & (0xfffffffeu << b);
                    }
                }
#pragma unroll
                for (int q = 0; q < NW; q++) skw[q] = kw[q];
            }
            __syncthreads();
            // ---- emit kept rows from precomputed row data ----
            for (int t = tid; t < M; t += 512) {
                if ((skw[t >> 5] >> (t & 31)) & 1u) {
                    int r = sr[t];
                    int slot = c * CAP2 + t;
#pragma unroll
                    for (int q = 0; q < 6; q++) out[6 * r + q] = d_crow6[slot * 6 + q];
                }
            }
        } else {
            // ---- mid path (MMASK < M <= CAP2): pivot loop ----
            unsigned char* skbyte = (unsigned char*)smask;   // 8192B >= CAP2
            for (int t = tid; t < M; t += 512) skbyte[t] = 1;
            __syncthreads();
            for (int i = 0; i < M - 1; i++) {
                __syncthreads();
                if (!skbyte[i]) continue;
                float xi1 = sx1[i], yi1 = sy1[i], xi2 = sx2[i], yi2 = sy2[i], ai = sar[i];
                for (int j = i + 1 + tid; j < M; j += 512) {
                    if (!skbyte[j]) continue;
                    if (sup_test(xi1, yi1, xi2, yi2, ai,
                                 sx1[j], sy1[j], sx2[j], sy2[j], sar[j]))
                        skbyte[j] = 0;
                }
            }
            __syncthreads();
            for (int t = tid; t < M; t += 512) {
                if (skbyte[t]) {
                    int r = sr[t];
                    int slot = c * CAP2 + t;
#pragma unroll
                    for (int q = 0; q < 6; q++) out[6 * r + q] = d_crow6[slot * 6 + q];
                }
            }
        }
    } else {
        // ---- fallback (M > CAP2, never expected): global pivot loop via d_cand ----
        unsigned char* skbyte = (unsigned char*)sx1;     // 4096B*? sx1 = 4KB... use sx1..sar = 20KB >= 8000
        for (int t = tid; t < M; t += 512) skbyte[t] = 1;
        __syncthreads();
        for (int i = 0; i < M - 1; i++) {
            __syncthreads();
            if (!skbyte[i]) continue;
            int oi = d_cand[c * NBOX + i] >> 16;
            float cx = d_dec6[oi * 6 + 0], cy = d_dec6[oi * 6 + 1];
            float w  = d_dec6[oi * 6 + 2], h  = d_dec6[oi * 6 + 3];
            float xi1 = cx - 0.5f * w, yi1 = cy - 0.5f * h;
            float xi2 = cx + 0.5f * w, yi2 = cy + 0.5f * h;
            float ai = fabsf((xi2 - xi1) * (yi2 - yi1));
            for (int j = i + 1 + tid; j < M; j += 512) {
                if (!skbyte[j]) continue;
                int oj = d_cand[c * NBOX + j] >> 16;
                float cxj = d_dec6[oj * 6 + 0], cyj = d_dec6[oj * 6 + 1];
                float wj  = d_dec6[oj * 6 + 2], hj  = d_dec6[oj * 6 + 3];
                float xj1 = cxj - 0.5f * wj, yj1 = cyj - 0.5f * hj;
                float xj2 = cxj + 0.5f * wj, yj2 = cyj + 0.5f * hj;
                float aj = fabsf((xj2 - xj1) * (yj2 - yj1));
                if (sup_test(xi1, yi1, xi2, yi2, ai, xj1, yj1, xj2, yj2, aj))
                    skbyte[j] = 0;
            }
        }
        __syncthreads();
        for (int t = tid; t < M; t += 512) {
            if (skbyte[t]) {
                int p = d_cand[c * NBOX + t];
                int r = p & 0xffff, orig = p >> 16;
#pragma unroll
                for (int q = 0; q < 6; q++) out[6 * r + q] = d_dec6[orig * 6 + q];
            }
        }
    }
}

// ---------------- launch ----------------
extern "C" void kernel_launch(void* const* d_in, const int* in_sizes, int n_in,
                              void* d_out, int out_size) {
    const float* x;
    const float* anchors;
    if (in_sizes[0] == 10) { anchors = (const float*)d_in[0]; x = (const float*)d_in[1]; }
    else                   { x = (const float*)d_in[0]; anchors = (const float*)d_in[1]; }
    float* out = (float*)d_out;

    k_decode <<<32, 256>>>(x, anchors, out);
    k_rank   <<<IGROUPS * JC, 256>>>();
    k_scatter<<<32, 256>>>();
    k_nms    <<<NCLS, 512>>>(out);
}